// round 4
// baseline (speedup 1.0000x reference)
#include <cuda_runtime.h>
#include <math.h>

// ContrastMemory: B=128, D=128, K+1=4097, N=100000, T=0.07, momentum=0.5
//
// Single persistent kernel, grid = 592 blocks (148 SMs x 4, co-resident by
// __launch_bounds__(256,4)), two phases separated by a counter grid-sync:
//   Phase 1: gather/dot/exp (out_v1, out_v2 unscaled) interleaved with the
//            full bank copy (DRAM-bound, overlaps the L2-bound gather).
//            Per-block partial sums -> g_part (no atomics, no init kernel).
//   Phase 2: every block reduces g_part, scales out_v1/out_v2 by
//            (B*K1)/(N*sum), and blocks < B apply the momentum row update.
//
// Inputs: v1[B,D] f32, v2[B,D] f32, idx[B,K+1] i32, y[B] i32,
//         memory_v1[N,D] f32, memory_v2[N,D] f32
// Output: out_v1[B*(K+1)] | out_v2[B*(K+1)] | new_mem_v1[N*D] | new_mem_v2[N*D]

#define D_DIM  128
#define T_INV  (1.0f / 0.07f)
#define MOM    0.5f
#define GRID   592
#define BLOCK  256
#define NWARP  8

__device__ double       g_part[GRID * 2];
__device__ unsigned int g_arrive = 0;
__device__ unsigned int g_done   = 0;

// Merged 2-value warp reduction: lanes 0-15 end with sum(d1), 16-31 with sum(d2).
__device__ __forceinline__ float reduce2(float d1, float d2, int lane) {
    float t = __shfl_xor_sync(0xFFFFFFFFu, d1, 16);
    float u = __shfl_xor_sync(0xFFFFFFFFu, d2, 16);
    float a = (lane < 16) ? (d1 + t) : (d2 + u);
    a += __shfl_xor_sync(0xFFFFFFFFu, a, 8);
    a += __shfl_xor_sync(0xFFFFFFFFu, a, 4);
    a += __shfl_xor_sync(0xFFFFFFFFu, a, 2);
    a += __shfl_xor_sync(0xFFFFFFFFu, a, 1);
    return a;
}

__device__ __forceinline__ float dot4(float4 p, float4 q) {
    return p.x * q.x + p.y * q.y + p.z * q.z + p.w * q.w;
}

__global__ __launch_bounds__(BLOCK, 4)
void fused_kernel(const float* __restrict__ v1, const float* __restrict__ v2,
                  const int* __restrict__ idx, const int* __restrict__ y,
                  const float* __restrict__ m1, const float* __restrict__ m2,
                  float* __restrict__ out1, float* __restrict__ out2,
                  float* __restrict__ o_m1, float* __restrict__ o_m2,
                  int B, int K1, long n4,
                  int TPB, int NITEM, long csz, float factor_base)
{
    const int tid  = threadIdx.x;
    const int lane = tid & 31;
    const int warp = tid >> 5;

    const float4* __restrict__ m1v = reinterpret_cast<const float4*>(m1);
    const float4* __restrict__ m2v = reinterpret_cast<const float4*>(m2);

    float sacc = 0.f;  // lane0 accumulates e1-sum, lane16 e2-sum

    // ---------------- Phase 1: dot tiles + bank copy, interleaved ----------------
    for (int id = blockIdx.x; id < NITEM; id += GRID) {
        const int q   = id / 5;
        const int rem = id - q * 5;

        if (rem == 4) {
            // copy chunk q: contiguous float4 range of both banks
            const float4* s1 = reinterpret_cast<const float4*>(m1);
            const float4* s2 = reinterpret_cast<const float4*>(m2);
            float4* d1 = reinterpret_cast<float4*>(o_m1);
            float4* d2 = reinterpret_cast<float4*>(o_m2);
            long base = (long)q * csz;
            long end  = base + csz; if (end > n4) end = n4;
            for (long i = base + tid; i < end; i += BLOCK) {
                float4 a = s1[i];
                float4 b = s2[i];
                __stcs(&d1[i], a);
                __stcs(&d2[i], b);
            }
            continue;
        }

        // dot tile
        const int t     = q * 4 + rem;          // 0 .. B*TPB-1
        const int b     = t / TPB;
        const int chunk = t - b * TPB;
        const int kb    = chunk * 256 + warp * 32;
        if (kb >= K1) continue;

        int cnt = K1 - kb; if (cnt > 32) cnt = 32;

        const int* __restrict__ idxb = idx + (long)b * K1;
        // one coalesced idx load covers this warp's 32 k's
        const int rv = (lane < cnt) ? idxb[kb + lane] : 0;

        const float4 a1 = reinterpret_cast<const float4*>(v1 + (long)b * D_DIM)[lane];
        const float4 a2 = reinterpret_cast<const float4*>(v2 + (long)b * D_DIM)[lane];

        float* __restrict__ ob1 = out1 + (long)b * K1 + kb;
        float* __restrict__ ob2 = out2 + (long)b * K1 + kb;

        int j = 0;
        for (; j + 4 <= cnt; j += 4) {
            const int r0 = __shfl_sync(0xFFFFFFFFu, rv, j);
            const int r1 = __shfl_sync(0xFFFFFFFFu, rv, j + 1);
            const int r2 = __shfl_sync(0xFFFFFFFFu, rv, j + 2);
            const int r3 = __shfl_sync(0xFFFFFFFFu, rv, j + 3);

            const float4 x0 = m1v[(long)r0 * 32 + lane];
            const float4 y0 = m2v[(long)r0 * 32 + lane];
            const float4 x1 = m1v[(long)r1 * 32 + lane];
            const float4 y1 = m2v[(long)r1 * 32 + lane];
            const float4 x2 = m1v[(long)r2 * 32 + lane];
            const float4 y2 = m2v[(long)r2 * 32 + lane];
            const float4 x3 = m1v[(long)r3 * 32 + lane];
            const float4 y3 = m2v[(long)r3 * 32 + lane];

            // out_v1 uses m2-row vs v1; out_v2 uses m1-row vs v2
            const float s0 = reduce2(dot4(y0, a1), dot4(x0, a2), lane);
            const float s1 = reduce2(dot4(y1, a1), dot4(x1, a2), lane);
            const float s2 = reduce2(dot4(y2, a1), dot4(x2, a2), lane);
            const float s3 = reduce2(dot4(y3, a1), dot4(x3, a2), lane);

            const float e0 = __expf(s0 * T_INV);
            const float e1 = __expf(s1 * T_INV);
            const float e2 = __expf(s2 * T_INV);
            const float e3 = __expf(s3 * T_INV);

            if (lane == 0) {
                ob1[j] = e0; ob1[j + 1] = e1; ob1[j + 2] = e2; ob1[j + 3] = e3;
                sacc += e0 + e1 + e2 + e3;
            } else if (lane == 16) {
                ob2[j] = e0; ob2[j + 1] = e1; ob2[j + 2] = e2; ob2[j + 3] = e3;
                sacc += e0 + e1 + e2 + e3;
            }
        }
        for (; j < cnt; j++) {
            const int r = __shfl_sync(0xFFFFFFFFu, rv, j);
            const float4 x  = m1v[(long)r * 32 + lane];
            const float4 yv = m2v[(long)r * 32 + lane];
            const float s = reduce2(dot4(yv, a1), dot4(x, a2), lane);
            const float e = __expf(s * T_INV);
            if (lane == 0)       { ob1[j] = e; sacc += e; }
            else if (lane == 16) { ob2[j] = e; sacc += e; }
        }
    }

    // -------- block-local sum -> g_part, then grid sync --------
    __shared__ float sh1[NWARP], sh2[NWARP];
    if (lane == 0)  sh1[warp] = sacc;
    if (lane == 16) sh2[warp] = sacc;
    __syncthreads();
    if (tid == 0) {
        double t1 = 0.0, t2 = 0.0;
        #pragma unroll
        for (int w = 0; w < NWARP; w++) { t1 += (double)sh1[w]; t2 += (double)sh2[w]; }
        g_part[2 * blockIdx.x]     = t1;
        g_part[2 * blockIdx.x + 1] = t2;
        __threadfence();
        atomicAdd(&g_arrive, 1u);
        // spin until all blocks arrive
        while (*((volatile unsigned int*)&g_arrive) < GRID) { __nanosleep(64); }
        __threadfence();
    }
    __syncthreads();

    // ---------------- Phase 2: reduce partials, scale, update rows ----------------
    __shared__ double shd1[NWARP], shd2[NWARP];
    {
        double s1 = 0.0, s2 = 0.0;
        for (int i = tid; i < GRID; i += BLOCK) {
            s1 += g_part[2 * i];
            s2 += g_part[2 * i + 1];
        }
        #pragma unroll
        for (int o = 16; o > 0; o >>= 1) {
            s1 += __shfl_xor_sync(0xFFFFFFFFu, s1, o);
            s2 += __shfl_xor_sync(0xFFFFFFFFu, s2, o);
        }
        if (lane == 0) { shd1[warp] = s1; shd2[warp] = s2; }
    }
    __syncthreads();

    double sum1 = 0.0, sum2 = 0.0;
    #pragma unroll
    for (int w = 0; w < NWARP; w++) { sum1 += shd1[w]; sum2 += shd2[w]; }
    const float inv1 = (float)((double)factor_base / sum1);
    const float inv2 = (float)((double)factor_base / sum2);

    // scale both out arrays (contiguous span, float4; B*K1 divisible by 4)
    {
        const long total4    = ((long)2 * B * K1) >> 2;
        const long boundary4 = ((long)B * K1) >> 2;
        float4* o = reinterpret_cast<float4*>(out1);
        for (long i = (long)blockIdx.x * BLOCK + tid; i < total4; i += (long)GRID * BLOCK) {
            float4 v = o[i];
            const float f = (i < boundary4) ? inv1 : inv2;
            v.x *= f; v.y *= f; v.z *= f; v.w *= f;
            o[i] = v;
        }
    }

    // momentum update + l2-normalize for the B touched rows (overwrites copy)
    if (blockIdx.x < B && warp == 0) {
        const int bb  = blockIdx.x;
        const int row = y[bb];
        {
            float4 mv = m1v[(long)row * 32 + lane];
            float4 vv = reinterpret_cast<const float4*>(v1 + (long)bb * D_DIM)[lane];
            float4 u;
            u.x = MOM * mv.x + (1.f - MOM) * vv.x;
            u.y = MOM * mv.y + (1.f - MOM) * vv.y;
            u.z = MOM * mv.z + (1.f - MOM) * vv.z;
            u.w = MOM * mv.w + (1.f - MOM) * vv.w;
            float n = u.x * u.x + u.y * u.y + u.z * u.z + u.w * u.w;
            #pragma unroll
            for (int o = 16; o > 0; o >>= 1) n += __shfl_xor_sync(0xFFFFFFFFu, n, o);
            const float invn = 1.f / sqrtf(n);
            u.x *= invn; u.y *= invn; u.z *= invn; u.w *= invn;
            reinterpret_cast<float4*>(o_m1 + (long)row * D_DIM)[lane] = u;
        }
        {
            float4 mv = m2v[(long)row * 32 + lane];
            float4 vv = reinterpret_cast<const float4*>(v2 + (long)bb * D_DIM)[lane];
            float4 u;
            u.x = MOM * mv.x + (1.f - MOM) * vv.x;
            u.y = MOM * mv.y + (1.f - MOM) * vv.y;
            u.z = MOM * mv.z + (1.f - MOM) * vv.z;
            u.w = MOM * mv.w + (1.f - MOM) * vv.w;
            float n = u.x * u.x + u.y * u.y + u.z * u.z + u.w * u.w;
            #pragma unroll
            for (int o = 16; o > 0; o >>= 1) n += __shfl_xor_sync(0xFFFFFFFFu, n, o);
            const float invn = 1.f / sqrtf(n);
            u.x *= invn; u.y *= invn; u.z *= invn; u.w *= invn;
            reinterpret_cast<float4*>(o_m2 + (long)row * D_DIM)[lane] = u;
        }
    }

    // -------- counter reset protocol (last finished block resets both) --------
    __syncthreads();
    if (tid == 0) {
        __threadfence();
        const unsigned int d = atomicAdd(&g_done, 1u);
        if (d == GRID - 1) {
            g_arrive = 0;
            g_done   = 0;
            __threadfence();
        }
    }
}

extern "C" void kernel_launch(void* const* d_in, const int* in_sizes, int n_in,
                              void* d_out, int out_size)
{
    const float* v1  = (const float*)d_in[0];
    const float* v2  = (const float*)d_in[1];
    const int*   idx = (const int*)d_in[2];
    const int*   y   = (const int*)d_in[3];
    const float* m1  = (const float*)d_in[4];
    const float* m2  = (const float*)d_in[5];

    const int  B  = in_sizes[3];               // 128
    const int  K1 = in_sizes[2] / B;           // 4097
    const long ND = in_sizes[4];               // N * D
    const int  N  = (int)(ND / D_DIM);         // 100000

    float* out  = (float*)d_out;
    float* out1 = out;                         // [B*K1]
    float* out2 = out + (long)B * K1;          // [B*K1]
    float* o_m1 = out + 2L * B * K1;           // [N*D]
    float* o_m2 = o_m1 + ND;                   // [N*D]

    const long n4    = ND / 4;                 // float4 count per bank
    const int  TPB   = (K1 + 255) / 256;       // dot tiles per sample (17)
    const int  NT    = B * TPB;                // 2176 dot tiles
    const int  NCOPY = (NT + 3) / 4;           // 544 copy chunks (1 per 4 dot tiles)
    const int  NITEM = NT + NCOPY;             // 2720 work items
    const long csz   = (n4 + NCOPY - 1) / NCOPY;

    const float factor_base = (float)((double)((long)B * K1) / (double)N);

    fused_kernel<<<GRID, BLOCK>>>(v1, v2, idx, y, m1, m2,
                                  out1, out2, o_m1, o_m2,
                                  B, K1, n4, TPB, NITEM, csz, factor_base);
}